// round 15
// baseline (speedup 1.0000x reference)
#include <cuda_runtime.h>
#include <cstdint>

#define MAX_PTS     128
#define GRID_R      128
#define NSTEPS      200

// ---------------------------------------------------------------------------
// voxel index: trunc(RN(s/CELL)), CELL = 3*2^-7. RN(s/CELL) = RN(s/3)*128
// exactly; RN(s/3) via Markstein two-FMA -> correctly rounded, bit-identical
// to __fdiv_rn. (int) truncates toward zero (numpy astype): s in (-CELL,0)
// maps to idx 0 (VALID) -> box expanded by one CELL on negative faces.
// ---------------------------------------------------------------------------
__device__ __forceinline__ int vox_idx(float s) {
    const float THIRD = 0.33333334f;            // RN(1/3)
    float q0 = __fmul_rn(s, THIRD);
    float rr = __fmaf_rn(-3.0f, q0, s);
    float q  = __fmaf_rn(rr, THIRD, q0);
    return (int)__fmul_rn(q, 128.0f);
}

// ---------------------------------------------------------------------------
// SINGLE fused kernel, one warp per ray, 256-thr blocks (8 rays).
//
// tn values come from a PER-LANE register fold: lane u needs tn[k0+u], which
// is exactly (k0+u+1) serial __fadd_rn(., STEP) from 2.0 — the identical op
// chain as the reference's t += STEP, so march decisions stay bit-exact.
// No smem table, no __syncthreads, no setup/pack kernels. Beyond k=199 the
// fold keeps going (finite, ~6.7); any tn > limit (<= 6) triggers "past",
// so no sentinel entries are needed.
//
// March: step-parallel (lane u probes step k0+u), single hit|past ballot,
// hit-over-past precedence via shfl. Slab entry skip / exit early-out on the
// truncation-expanded box ((-1.5-CELL, 1.5) per axis), 3-step margins.
// Occ probed directly (__ldg, L2-resident). March latency hides behind the
// t_rand DRAM prefetch.
//
// Sample: z linear in near -> z = near + (6-near)*c with
//   c = (j-0.5+tr)/127 interior, tr*0.5/127 at j=0, (126.5+0.5tr)/127 at 127;
// pts = (o+d*near) + d*(6-near)*c. Stores staged via smem, fully coalesced,
// streaming hint.
// ---------------------------------------------------------------------------
__global__ void __launch_bounds__(256) fused_kernel(
        const float* __restrict__ ro,
        const float* __restrict__ rd,
        const float* __restrict__ trand,
        const uint32_t* __restrict__ occ,
        float* __restrict__ out,
        int n) {
    __shared__ float4 psh[8 * 96];      // 12 KB pts staging

    const unsigned FULL = 0xffffffffu;
    int warp = threadIdx.x >> 5;
    int lane = threadIdx.x & 31;
    int r = (blockIdx.x << 3) + warp;
    if (r >= n) return;

    const float CELL = 0.0234375f;
    const float STEP = 0.5f * __fsqrt_rn(0.00164794921875f);   // exact fp32
    const float INV_STEP = 49.267f;     // approx 1/STEP; 3-step margin absorbs
    const float BMIN = -1.5f - CELL;    // truncation-expanded negative faces
    const float BMAX =  1.5f;
    const float INV127 = 0.007874016f;  // RN(1/127)

    // prefetch t_rand first: fold + slab + march latency hide behind it
    float4 t4 = __ldcs(reinterpret_cast<const float4*>(trand + (size_t)r * MAX_PTS) + lane);

    float ox = ro[3 * r + 0], oy = ro[3 * r + 1], oz = ro[3 * r + 2];
    float dx = rd[3 * r + 0], dy = rd[3 * r + 1], dz = rd[3 * r + 2];

    // ---- slab test on expanded box: lanes 0..2, butterfly-reduce ----
    float tlo = 0.0f, thi = 1e30f;
    if (lane < 3) {
        float o = (lane == 0) ? ox : (lane == 1) ? oy : oz;
        float d = (lane == 0) ? dx : (lane == 1) ? dy : dz;
        if (fabsf(d) > 1e-8f) {
            float inv = __frcp_rn(d);
            float t1 = (BMIN - o) * inv;
            float t2 = (BMAX - o) * inv;
            tlo = fminf(t1, t2);
            thi = fmaxf(t1, t2);
        } else if (o < BMIN - 0.001f || o > BMAX + 0.001f) {
            tlo = 1e9f;    // parallel & strictly outside -> never valid
        }
    }
#pragma unroll
    for (int off = 16; off; off >>= 1) {
        tlo = fmaxf(tlo, __shfl_xor_sync(FULL, tlo, off));
        thi = fminf(thi, __shfl_xor_sync(FULL, thi, off));
    }
    tlo = fminf(tlo, 1e8f);
    int k_start = (int)floorf((tlo - 2.0f) * INV_STEP) - 3;
    k_start = max(k_start, 0);
    k_start = min(k_start, NSTEPS - 1);   // final chunk always contains a past
    float limit = fminf(6.0f, thi + 3.0f * STEP);

    // ---- per-lane register fold up to step k_start+lane (bit-exact chain) --
    float tn = 2.0f;
    int nfold = k_start + lane + 1;       // tn[k] = (k+1) serial adds from 2.0
#pragma unroll 1
    for (int i = 0; i < nfold; i++) tn = __fadd_rn(tn, STEP);

    // ---- step-parallel march: lane u probes step k0+u ----
    float nn = 2.0f;
#pragma unroll 1
    for (int k0 = k_start; k0 < NSTEPS; k0 += 32) {
        float sx = __fadd_rn(__fadd_rn(ox, __fmul_rn(dx, tn)), 1.5f);
        float sy = __fadd_rn(__fadd_rn(oy, __fmul_rn(dy, tn)), 1.5f);
        float sz = __fadd_rn(__fadd_rn(oz, __fmul_rn(dz, tn)), 1.5f);
        int jx = vox_idx(sx);
        int jy = vox_idx(sy);
        int jz = vox_idx(sz);
        bool valid = ((unsigned)jx < 128u) & ((unsigned)jy < 128u) &
                     ((unsigned)jz < 128u);
        int hit = 0;
        if (valid) {
            int li = (jx << 14) | (jy << 7) | jz;
            hit = (__ldg(occ + li) != 0u);
        }
        bool past = (tn > limit);
        unsigned st = __ballot_sync(FULL, hit | (int)past);
        if (st) {
            int b = __ffs(st) - 1;                        // earliest stop step
            int isHit = __shfl_sync(FULL, hit, b);        // hit beats past
            float tnb = __shfl_sync(FULL, tn, b);
            nn = isHit ? fminf(tnb, 6.0f) : 6.0f;
            break;
        }
        // advance this lane's tn by 32 steps (identical fold chain)
#pragma unroll
        for (int i = 0; i < 32; i++) tn = __fadd_rn(tn, STEP);
    }
    float near_v = fminf(nn, 6.0f);

    // ---- stratified sampling: lane owns samples j0..j0+3 ----
    int j0 = lane << 2;
    float tr[4] = {t4.x, t4.y, t4.z, t4.w};

    float span = 6.0f - near_v;
    float bx = __fmaf_rn(dx, near_v, ox), ex = dx * span;
    float by = __fmaf_rn(dy, near_v, oy), ey = dy * span;
    float bz = __fmaf_rn(dz, near_v, oz), ez = dz * span;

    float c[4], zv[4];
#pragma unroll
    for (int i = 0; i < 4; i++) {
        int j = j0 + i;
        float ci;
        if (j == 0)        ci = tr[i] * (0.5f * INV127);
        else if (j == 127) ci = __fmaf_rn(tr[i], 0.5f, 126.5f) * INV127;
        else               ci = (tr[i] + ((float)j - 0.5f)) * INV127;
        c[i] = ci;
        zv[i] = __fmaf_rn(span, ci, near_v);
    }

    size_t total = (size_t)n * MAX_PTS;
    __stcs(reinterpret_cast<float4*>(out + total * 3) + (size_t)r * 32 + lane,
           make_float4(zv[0], zv[1], zv[2], zv[3]));

    // 12 contiguous pts floats for samples j0..j0+3, staged through smem
    float p[12];
#pragma unroll
    for (int i = 0; i < 4; i++) {
        p[3 * i + 0] = __fmaf_rn(ex, c[i], bx);
        p[3 * i + 1] = __fmaf_rn(ey, c[i], by);
        p[3 * i + 2] = __fmaf_rn(ez, c[i], bz);
    }
    float4* base = psh + warp * 96;
    base[3 * lane + 0] = make_float4(p[0], p[1], p[2],  p[3]);
    base[3 * lane + 1] = make_float4(p[4], p[5], p[6],  p[7]);
    base[3 * lane + 2] = make_float4(p[8], p[9], p[10], p[11]);
    __syncwarp();

    float4* pts4 = reinterpret_cast<float4*>(out) + (size_t)r * 96;
    __stcs(pts4 + lane +  0, base[lane +  0]);
    __stcs(pts4 + lane + 32, base[lane + 32]);
    __stcs(pts4 + lane + 64, base[lane + 64]);
}

// ---------------------------------------------------------------------------
extern "C" void kernel_launch(void* const* d_in, const int* in_sizes, int n_in,
                              void* d_out, int out_size) {
    const float*    ro  = (const float*)d_in[0];    // rays_o   [n,3]
    const float*    rd  = (const float*)d_in[1];    // viewdirs [n,3]
    const float*    tr  = (const float*)d_in[2];    // t_rand   [n,128]
    const uint32_t* occ = (const uint32_t*)d_in[3]; // occ_grid [128^3], 4B elems

    int n = in_sizes[0] / 3;

    fused_kernel<<<(n + 7) / 8, 256>>>(ro, rd, tr, occ, (float*)d_out, n);
}

// round 16
// speedup vs baseline: 1.2563x; 1.2563x over previous
#include <cuda_runtime.h>
#include <cstdint>

#define MAX_PTS     128
#define GRID_R      128
#define OCC_ELEMS   (GRID_R * GRID_R * GRID_R)        // 2097152
#define OCC_WORDS   (OCC_ELEMS / 32)                  // 65536 words = 256 KB
#define NSTEPS      200
#define TN_PAD      232                               // 200 real + 32 sentinel

__device__ uint32_t g_occ_bits[OCC_WORDS];
__device__ float    g_tn[TN_PAD];   // exact fp32 fold of t += STEP from 2.0

// ---------------------------------------------------------------------------
// Kernel 1: pack occupancy (4-byte elems). Thread loads uint4 (4 elems) ->
// nibble; 8-lane subgroups assemble a word via __reduce_or_sync. Thread (0,0)
// also builds the exact tn fold table: serial fp32 fold, bit-identical to the
// reference's t += STEP chain. STEP = fp32(0.5*sqrt(27/16384)) exact.
// Entries 200..231 are sentinels (always "past").
// ---------------------------------------------------------------------------
__global__ void pack_occ_kernel(const uint4* __restrict__ occ) {
    if (blockIdx.x == 0 && threadIdx.x == 0) {
        const float STEP = 0.5f * __fsqrt_rn(0.00164794921875f);
        float t = 2.0f;
        for (int k = 0; k < NSTEPS; k++) { t = __fadd_rn(t, STEP); g_tn[k] = t; }
        for (int k = NSTEPS; k < TN_PAD; k++) g_tn[k] = 1e9f;
    }
    int e = blockIdx.x * blockDim.x + threadIdx.x;    // one uint4 = 4 elems
    uint4 v = occ[e];
    unsigned nib = (v.x != 0u) | ((v.y != 0u) << 1) |
                   ((v.z != 0u) << 2) | ((v.w != 0u) << 3);
    int lane = threadIdx.x & 31;
    unsigned submask = 0xffu << (8 * (lane >> 3));
    unsigned word = __reduce_or_sync(submask, nib << (4 * (lane & 7)));
    if ((lane & 7) == 0) g_occ_bits[e >> 3] = word;
}

// ---------------------------------------------------------------------------
// voxel index: trunc(RN(s/CELL)), CELL = 3*2^-7. RN(s/CELL) = RN(s/3)*128
// exactly; RN(s/3) via Markstein two-FMA -> correctly rounded, bit-identical
// to __fdiv_rn. (int) truncates toward zero (numpy astype): s in (-CELL,0)
// maps to idx 0 (VALID) -> box expanded by one CELL on negative faces.
// ---------------------------------------------------------------------------
__device__ __forceinline__ int vox_idx(float s) {
    const float THIRD = 0.33333334f;            // RN(1/3)
    float q0 = __fmul_rn(s, THIRD);
    float rr = __fmaf_rn(-3.0f, q0, s);
    float q  = __fmaf_rn(rr, THIRD, q0);
    return (int)__fmul_rn(q, 128.0f);
}

// ---------------------------------------------------------------------------
// Kernel 2: fused march + sample, one WARP per ray. 128-thr blocks (4 rays):
// smaller CTAs shrink the march-straggler tail per CTA slot and double the
// scheduling granularity (32768 CTAs) vs the 256-thr variant.
//
// March: step-parallel (lane u probes step k0+u), single hit|past ballot,
// hit-over-past precedence via shfl at the stopping lane. Bit-exact
// decisions: fold table + exact divide + expanded-box slab, 3-step margins.
// March latency hides behind the t_rand DRAM prefetch.
//
// Sample: z linear in near -> z = near + (6-near)*c with
//   c = (j-0.5+tr)/127 interior, tr*0.5/127 at j=0, (126.5+0.5tr)/127 at 127;
// pts = (o+d*near) + d*(6-near)*c. Stores staged via smem, fully coalesced.
// ---------------------------------------------------------------------------
__global__ void __launch_bounds__(128) fused_kernel(
        const float* __restrict__ ro,
        const float* __restrict__ rd,
        const float* __restrict__ trand,
        float* __restrict__ out,
        int n) {
    __shared__ float4 psh[4 * 96];      // 6 KB pts staging

    const unsigned FULL = 0xffffffffu;
    int warp = threadIdx.x >> 5;
    int lane = threadIdx.x & 31;
    int r = (blockIdx.x << 2) + warp;
    if (r >= n) return;

    const float CELL = 0.0234375f;
    const float STEP = 0.5f * __fsqrt_rn(0.00164794921875f);
    const float INV_STEP = 49.267f;     // approx 1/STEP; 3-step margin absorbs
    const float BMIN = -1.5f - CELL;    // truncation-expanded negative faces
    const float BMAX =  1.5f;
    const float INV127 = 0.007874016f;  // RN(1/127)

    // prefetch t_rand early: march latency hides behind this load
    float4 t4 = __ldcs(reinterpret_cast<const float4*>(trand + (size_t)r * MAX_PTS) + lane);

    float ox = ro[3 * r + 0], oy = ro[3 * r + 1], oz = ro[3 * r + 2];
    float dx = rd[3 * r + 0], dy = rd[3 * r + 1], dz = rd[3 * r + 2];

    // ---- slab test on expanded box: lanes 0..2, butterfly-reduce ----
    float tlo = 0.0f, thi = 1e30f;
    if (lane < 3) {
        float o = (lane == 0) ? ox : (lane == 1) ? oy : oz;
        float d = (lane == 0) ? dx : (lane == 1) ? dy : dz;
        if (fabsf(d) > 1e-8f) {
            float inv = __frcp_rn(d);
            float t1 = (BMIN - o) * inv;
            float t2 = (BMAX - o) * inv;
            tlo = fminf(t1, t2);
            thi = fmaxf(t1, t2);
        } else if (o < BMIN - 0.001f || o > BMAX + 0.001f) {
            tlo = 1e9f;    // parallel & strictly outside -> never valid
        }
    }
#pragma unroll
    for (int off = 16; off; off >>= 1) {
        tlo = fmaxf(tlo, __shfl_xor_sync(FULL, tlo, off));
        thi = fminf(thi, __shfl_xor_sync(FULL, thi, off));
    }
    tlo = fminf(tlo, 1e8f);
    int k_start = (int)floorf((tlo - 2.0f) * INV_STEP) - 3;
    k_start = max(k_start, 0);
    k_start = min(k_start, NSTEPS - 1);   // final chunk always contains a past
    float limit = fminf(6.0f, thi + 3.0f * STEP);

    // ---- step-parallel march: lane u probes step k0+u ----
    float nn = 2.0f;
#pragma unroll 1
    for (int k0 = k_start; k0 < NSTEPS; k0 += 32) {
        float tn = __ldg(&g_tn[k0 + lane]);   // padded table: no bound check
        float sx = __fadd_rn(__fadd_rn(ox, __fmul_rn(dx, tn)), 1.5f);
        float sy = __fadd_rn(__fadd_rn(oy, __fmul_rn(dy, tn)), 1.5f);
        float sz = __fadd_rn(__fadd_rn(oz, __fmul_rn(dz, tn)), 1.5f);
        int jx = vox_idx(sx);
        int jy = vox_idx(sy);
        int jz = vox_idx(sz);
        bool valid = ((unsigned)jx < 128u) & ((unsigned)jy < 128u) &
                     ((unsigned)jz < 128u);
        int hit = 0;
        if (valid) {
            int li = (jx << 14) | (jy << 7) | jz;
            hit = (g_occ_bits[li >> 5] >> (li & 31)) & 1u;
        }
        bool past = (tn > limit);
        unsigned st = __ballot_sync(FULL, hit | (int)past);
        if (st) {
            int b = __ffs(st) - 1;                        // earliest stop step
            int isHit = __shfl_sync(FULL, hit, b);        // hit beats past
            float tnb = __shfl_sync(FULL, tn, b);
            nn = isHit ? fminf(tnb, 6.0f) : 6.0f;
            break;
        }
    }
    float near_v = fminf(nn, 6.0f);

    // ---- stratified sampling: lane owns samples j0..j0+3 ----
    int j0 = lane << 2;
    float tr[4] = {t4.x, t4.y, t4.z, t4.w};

    float span = 6.0f - near_v;
    float bx = __fmaf_rn(dx, near_v, ox), ex = dx * span;
    float by = __fmaf_rn(dy, near_v, oy), ey = dy * span;
    float bz = __fmaf_rn(dz, near_v, oz), ez = dz * span;

    float c[4], zv[4];
#pragma unroll
    for (int i = 0; i < 4; i++) {
        int j = j0 + i;
        float ci;
        if (j == 0)        ci = tr[i] * (0.5f * INV127);
        else if (j == 127) ci = __fmaf_rn(tr[i], 0.5f, 126.5f) * INV127;
        else               ci = (tr[i] + ((float)j - 0.5f)) * INV127;
        c[i] = ci;
        zv[i] = __fmaf_rn(span, ci, near_v);
    }

    size_t total = (size_t)n * MAX_PTS;
    __stcs(reinterpret_cast<float4*>(out + total * 3) + (size_t)r * 32 + lane,
           make_float4(zv[0], zv[1], zv[2], zv[3]));

    // 12 contiguous pts floats for samples j0..j0+3, staged through smem
    float p[12];
#pragma unroll
    for (int i = 0; i < 4; i++) {
        p[3 * i + 0] = __fmaf_rn(ex, c[i], bx);
        p[3 * i + 1] = __fmaf_rn(ey, c[i], by);
        p[3 * i + 2] = __fmaf_rn(ez, c[i], bz);
    }
    float4* base = psh + warp * 96;
    base[3 * lane + 0] = make_float4(p[0], p[1], p[2],  p[3]);
    base[3 * lane + 1] = make_float4(p[4], p[5], p[6],  p[7]);
    base[3 * lane + 2] = make_float4(p[8], p[9], p[10], p[11]);
    __syncwarp();

    float4* pts4 = reinterpret_cast<float4*>(out) + (size_t)r * 96;
    __stcs(pts4 + lane +  0, base[lane +  0]);
    __stcs(pts4 + lane + 32, base[lane + 32]);
    __stcs(pts4 + lane + 64, base[lane + 64]);
}

// ---------------------------------------------------------------------------
extern "C" void kernel_launch(void* const* d_in, const int* in_sizes, int n_in,
                              void* d_out, int out_size) {
    const float* ro  = (const float*)d_in[0];    // rays_o   [n,3]
    const float* rd  = (const float*)d_in[1];    // viewdirs [n,3]
    const float* tr  = (const float*)d_in[2];    // t_rand   [n,128]
    const uint4* occ = (const uint4*)d_in[3];    // occ_grid [128^3], 4B elems

    int n = in_sizes[0] / 3;

    pack_occ_kernel<<<OCC_ELEMS / 4 / 256, 256>>>(occ);
    fused_kernel<<<(n + 3) / 4, 128>>>(ro, rd, tr, (float*)d_out, n);
}